// round 16
// baseline (speedup 1.0000x reference)
#include <cuda_runtime.h>
#include <cuda_fp16.h>
#include <math.h>
#include <stdint.h>

// ---------------- problem constants ----------------
constexpr int cT   = 2048;
constexpr int cD   = 1024;
constexpr int cV   = 32000;
constexpr int cE   = 16;
constexpr int cK   = 2;
constexpr int cCAP = 512;
constexpr int cDH  = 64;
constexpr int cDFF = 4096;

// ---------------- device scratch ----------------
__device__ float g_h   [cT * cD];
__device__ float g_cos [cT * cDH];
__device__ float g_sin [cT * cDH];
__device__ float g_logits[cT * cE];
__device__ float g_probs [cT * cE];
__device__ unsigned char g_mask[cT * cE];
__device__ int   g_kept_slot[cT * cE];
__device__ int   g_counts[cE];
__device__ int   g_etok[cE * cCAP];
__device__ float g_eout[(long)cE * cCAP * cD];
__device__ __half g_xinh[(long)cE * cCAP * cD];
__device__ __half g_xinl[(long)cE * cCAP * cD];
__device__ __half g_midh[(long)cE * cCAP * cDFF];
__device__ __half g_midl[(long)cE * cCAP * cDFF];
__device__ __half g_w1h [(long)cE * cDFF * cD];
__device__ __half g_w1l [(long)cE * cDFF * cD];
__device__ __half g_w2h [(long)cE * cD * cDFF];
__device__ __half g_w2l [(long)cE * cD * cDFF];
__device__ __half g_hnh [cT * cD];
__device__ __half g_ewh [(long)cV * cD];

// ---------------- common helpers ----------------
__device__ __forceinline__ uint32_t s2u(const void* p) {
    uint32_t a;
    asm("{ .reg .u64 t; cvta.to.shared.u64 t, %1; cvt.u32.u64 %0, t; }" : "=r"(a) : "l"(p));
    return a;
}
__device__ __forceinline__ void mma16816(float& c0, float& c1, float& c2, float& c3,
                                         uint32_t a0, uint32_t a1, uint32_t a2, uint32_t a3,
                                         uint32_t b0, uint32_t b1) {
    asm volatile(
        "mma.sync.aligned.m16n8k16.row.col.f32.f16.f16.f32 "
        "{%0,%1,%2,%3}, {%4,%5,%6,%7}, {%8,%9}, {%0,%1,%2,%3};"
        : "+f"(c0), "+f"(c1), "+f"(c2), "+f"(c3)
        : "r"(a0), "r"(a1), "r"(a2), "r"(a3), "r"(b0), "r"(b1));
}
__device__ __forceinline__ void cpa16(uint32_t dst, const void* src, int sz) {
    asm volatile("cp.async.cg.shared.global [%0], [%1], 16, %2;"
                 :: "r"(dst), "l"(src), "r"(sz) : "memory");
}
__device__ __forceinline__ void split_h(float x, __half& hi, __half& lo) {
    hi = __float2half_rn(x);
    lo = __float2half_rn(x - __half2float(hi));
}
__device__ __forceinline__ float gelu1(float x) {
    return 0.5f * x * (1.0f + tanhf(0.7978845608028654f * (x + 0.044715f * x * x * x)));
}

// top-2 + softmax + mask/slot-reset for token t, given 16 logits (single thread)
__device__ __forceinline__ void route_token(int t, const float* l) {
    int i1 = 0; float v1 = l[0];
    #pragma unroll
    for (int e = 1; e < cE; e++) if (l[e] > v1) { v1 = l[e]; i1 = e; }
    int i2 = -1; float v2 = -INFINITY;
    #pragma unroll
    for (int e = 0; e < cE; e++) if (e != i1 && l[e] > v2) { v2 = l[e]; i2 = e; }
    float sum = 0.f; float p[cE];
    #pragma unroll
    for (int e = 0; e < cE; e++) { p[e] = expf(l[e] - v1); sum += p[e]; }
    float invs = 1.0f / sum;
    #pragma unroll
    for (int e = 0; e < cE; e++) {
        g_probs[t * cE + e] = p[e] * invs;
        g_mask [t * cE + e] = (e == i1 || e == i2) ? 1 : 0;
        g_kept_slot[t * cE + e] = -1;
    }
}

// ---------------- small kernels ----------------
__global__ void rope_init_kernel() {
    int t = blockIdx.x;
    int i = threadIdx.x;
    int j = 2 * (i & 31);
    float inv = powf(10000.0f, -(float)j / (float)cDH);
    float fr  = (float)t * inv;
    g_cos[t * cDH + i] = cosf(fr);
    g_sin[t * cDH + i] = sinf(fr);
}

__global__ void embed_gather_kernel(const int* __restrict__ ids,
                                    const float* __restrict__ ew) {
    long q = ((long)blockIdx.x * blockDim.x + threadIdx.x) * 4;
    if (q >= (long)cT * cD) return;
    int t = (int)(q >> 10);
    int d = (int)(q & (cD - 1));
    *(float4*)&g_h[q] = *(const float4*)&ew[(long)ids[t] * cD + d];
}

__global__ void ew_half_kernel(const float* __restrict__ ew) {
    long idx = ((long)blockIdx.x * blockDim.x + threadIdx.x) * 2;
    if (idx >= (long)cV * cD) return;
    float2 v = *(const float2*)&ew[idx];
    *(__half2*)&g_ewh[idx] = __halves2half2(__float2half_rn(v.x), __float2half_rn(v.y));
}

// fused: router logits + top-2 + softmax + slot reset (hop 0)
__global__ void router_route_kernel(const float* __restrict__ wr) {
    int t    = blockIdx.x;
    int e    = threadIdx.x >> 5;
    int lane = threadIdx.x & 31;
    __shared__ float lg[cE];
    float s = 0.f;
    const float* hp = &g_h[(long)t * cD];
    for (int d = lane; d < cD; d += 32)
        s += hp[d] * wr[(long)d * cE + e];
    #pragma unroll
    for (int o = 16; o; o >>= 1) s += __shfl_down_sync(0xffffffffu, s, o);
    if (lane == 0) { lg[e] = s; g_logits[t * cE + e] = s; }
    __syncthreads();
    if (threadIdx.x == 0) {
        route_token(t, lg);
        if (t < cE) g_counts[t] = 0;
    }
}

// fused: combine (prev hop) + router logits + top-2 + softmax (next hop)
__global__ void combine_router_route_kernel(const float* __restrict__ wr) {
    int t = blockIdx.x;
    __shared__ float hx[cD];
    __shared__ float lg[cE];
    __shared__ int   s_ne, s_ke[cK], s_ks[cK];
    __shared__ float s_kp[cK], s_rho;
    if (threadIdx.x == 0) {
        int ne = 0; float rho = 0.f;
        #pragma unroll
        for (int e = 0; e < cE; e++) {
            int sl = g_kept_slot[t * cE + e];
            if (sl >= 0) {
                float p = g_probs[t * cE + e];
                rho += p;
                if (ne < cK) { s_ke[ne] = e; s_ks[ne] = sl; s_kp[ne] = p; ne++; }
            }
        }
        s_ne = ne; s_rho = rho;
    }
    __syncthreads();
    int ne = s_ne; float rho = s_rho;
    for (int d = threadIdx.x; d < cD; d += 512) {
        float hv = g_h[(long)t * cD + d];
        float comb = 0.f;
        for (int q = 0; q < ne; q++)
            comb += s_kp[q] * g_eout[((long)(s_ke[q] * cCAP + s_ks[q])) * cD + d];
        float hn = hv + comb - rho * hv;
        hx[d] = hn;
        g_h[(long)t * cD + d] = hn;
    }
    __syncthreads();
    int e = threadIdx.x >> 5, lane = threadIdx.x & 31;
    float s = 0.f;
    for (int d = lane; d < cD; d += 32)
        s += hx[d] * wr[(long)d * cE + e];
    #pragma unroll
    for (int o = 16; o; o >>= 1) s += __shfl_down_sync(0xffffffffu, s, o);
    if (lane == 0) { lg[e] = s; g_logits[t * cE + e] = s; }
    __syncthreads();
    if (threadIdx.x == 0) {
        route_token(t, lg);
        if (t < cE) g_counts[t] = 0;
    }
}

// fused: final combine + rmsnorm -> fp16 (h never written back to global)
__global__ void combine_rmsnorm_kernel(const float* __restrict__ lns) {
    int t = blockIdx.x;
    __shared__ float red[256];
    __shared__ int   s_ne, s_ke[cK], s_ks[cK];
    __shared__ float s_kp[cK], s_rho;
    if (threadIdx.x == 0) {
        int ne = 0; float rho = 0.f;
        #pragma unroll
        for (int e = 0; e < cE; e++) {
            int sl = g_kept_slot[t * cE + e];
            if (sl >= 0) {
                float p = g_probs[t * cE + e];
                rho += p;
                if (ne < cK) { s_ke[ne] = e; s_ks[ne] = sl; s_kp[ne] = p; ne++; }
            }
        }
        s_ne = ne; s_rho = rho;
    }
    __syncthreads();
    int ne = s_ne; float rho = s_rho;
    float hn[4];
    float ss = 0.f;
    #pragma unroll
    for (int j = 0; j < 4; j++) {
        int d = threadIdx.x + 256 * j;
        float hv = g_h[(long)t * cD + d];
        float comb = 0.f;
        for (int q = 0; q < ne; q++)
            comb += s_kp[q] * g_eout[((long)(s_ke[q] * cCAP + s_ks[q])) * cD + d];
        hn[j] = hv + comb - rho * hv;
        ss += hn[j] * hn[j];
    }
    red[threadIdx.x] = ss;
    __syncthreads();
    #pragma unroll
    for (int o = 128; o; o >>= 1) {
        if (threadIdx.x < o) red[threadIdx.x] += red[threadIdx.x + o];
        __syncthreads();
    }
    float inv = rsqrtf(red[0] / (float)cD + 1e-6f);
    #pragma unroll
    for (int j = 0; j < 4; j++) {
        int d = threadIdx.x + 256 * j;
        g_hnh[(long)t * cD + d] = __float2half_rn(hn[j] * lns[d] * inv);
    }
}

__global__ void capacity_kernel() {
    int e = blockIdx.x;
    __shared__ int   cnt;
    __shared__ int   idx[cT];
    __shared__ float val[cT];
    if (threadIdx.x == 0) cnt = 0;
    __syncthreads();
    for (int t = threadIdx.x; t < cT; t += blockDim.x) {
        if (g_mask[t * cE + e]) {
            int p = atomicAdd(&cnt, 1);
            idx[p] = t;
            val[p] = g_logits[t * cE + e];
        }
    }
    __syncthreads();
    int n = cnt;
    for (int i = threadIdx.x; i < n; i += blockDim.x) {
        float v = val[i]; int t = idx[i];
        int rank = 0;
        for (int j = 0; j < n; j++) {
            float u = val[j]; int s = idx[j];
            rank += (u > v || (u == v && s < t)) ? 1 : 0;
        }
        if (rank < cCAP) {
            int slot = atomicAdd(&g_counts[e], 1);
            g_etok[e * cCAP + slot] = t;
            g_kept_slot[t * cE + e] = slot;
        }
    }
}

// gather + RoPE + fp16 split; WLO=0 skips the lo-half write (hop-2: never read)
template<int WLO>
__global__ void gather_rope_kernel() {
    int c = blockIdx.x;
    int e = blockIdx.y;
    if (c >= g_counts[e]) return;
    int t = g_etok[e * cCAP + c];
    __shared__ float x[cD];
    for (int d = threadIdx.x; d < cD; d += blockDim.x) x[d] = g_h[(long)t * cD + d];
    __syncthreads();
    const float* cs = &g_cos[t * cDH];
    const float* sn = &g_sin[t * cDH];
    long base = ((long)(e * cCAP + c)) * cD;
    for (int dp = threadIdx.x; dp < cD / 2; dp += blockDim.x) {
        int d0 = dp * 2;
        float o[2];
        #pragma unroll
        for (int q = 0; q < 2; q++) {
            int d = d0 + q;
            int i = d & (cDH - 1);
            float r = (i < 32) ? -x[d + 32] : x[d - 32];
            o[q] = x[d] * cs[i] + r * sn[i];
        }
        __half h0, l0, h1, l1;
        split_h(o[0], h0, l0);
        split_h(o[1], h1, l1);
        *(__half2*)&g_xinh[base + d0] = __halves2half2(h0, h1);
        if (WLO) *(__half2*)&g_xinl[base + d0] = __halves2half2(l0, l1);
    }
}

__global__ void split_transpose_kernel(const float* __restrict__ in,
                                       __half* __restrict__ oh, __half* __restrict__ ol,
                                       int R, int C) {
    __shared__ float tile[32][33];
    long eoff = (long)blockIdx.z * R * C;
    int c0 = blockIdx.x * 32, r0 = blockIdx.y * 32;
    int x = threadIdx.x, y = threadIdx.y;
    #pragma unroll
    for (int i = 0; i < 32; i += 8)
        tile[y + i][x] = in[eoff + (long)(r0 + y + i) * C + c0 + x];
    __syncthreads();
    if (x < 16) {
        #pragma unroll
        for (int i = 0; i < 32; i += 8) {
            int nl = y + i;
            float v0 = tile[2 * x][nl];
            float v1 = tile[2 * x + 1][nl];
            __half h0, l0, h1, l1;
            split_h(v0, h0, l0);
            split_h(v1, h1, l1);
            long o = eoff + (long)(c0 + nl) * R + r0 + 2 * x;
            *(__half2*)&oh[o] = __halves2half2(h0, h1);
            *(__half2*)&ol[o] = __halves2half2(l0, l1);
        }
    }
}

// ---------------- pre-split fp16 GEMM (experts) ----------------
// BM=64: 8 warps as 2M x 4N (warp tile 32x32) -- proven best tile shape.
// NPASS=3: ah*bh + ah*bl + al*bh (routing-safe); NPASS=1: ah*bh only.
// OUT: 0 = fp32, 1 = f16 hi+lo, 2 = f16 hi only.
constexpr int HSTR  = 20;
constexpr int BSEG  = 128 * HSTR;

template<int ACT, int OUT, int NPASS, int BM>
__global__ void __launch_bounds__(256, 2)
hgemm_ps(const __half* __restrict__ Ah, const __half* __restrict__ Al,
         const __half* __restrict__ Bh, const __half* __restrict__ Bl,
         float* __restrict__ Cf, __half* __restrict__ Ch, __half* __restrict__ Cl,
         int Kd, int ldc,
         long sA, long sB, long sC, const int* __restrict__ Mvec)
{
    constexpr int MW   = BM / 32;
    constexpr int NW   = 8 / MW;
    constexpr int NI   = 128 / (NW * 8);
    constexpr int ASEG = BM * HSTR;
    constexpr int ALO  = (NPASS == 3) ? ASEG : 0;
    constexpr int BH_OFF = ASEG + ALO;
    constexpr int BLO  = (NPASS >= 2) ? BSEG : 0;
    constexpr int STG  = BH_OFF + BSEG + BLO;

    extern __shared__ uint32_t sh[];
    int e  = blockIdx.z;
    int Me = Mvec[e];
    int bm = blockIdx.y * BM;
    if (bm >= Me) return;
    int bn = blockIdx.x * 128;
    const __half* Ahp = Ah + (long)e * sA;
    const __half* Alp = Al + (long)e * sA;
    const __half* Bhp = Bh + (long)e * sB;
    const __half* Blp = Bl + (long)e * sB;

    int tid = threadIdx.x;
    int wid = tid >> 5, lane = tid & 31;
    int g   = lane >> 2, tg = lane & 3;
    int wm  = (wid % MW) * 32;
    int wn  = (wid / MW) * (NI * 8);

    uint32_t smu = s2u(sh);

    auto load_stage = [&](int s, int k0) {
        uint32_t b0 = smu + (s * STG) * 4;
        #pragma unroll
        for (int j = 0; j < BM / 64; j++) {
            int q = tid + 256 * j;
            int row = q >> 2, c4 = q & 3;
            int ok = (bm + row) < Me;
            long so = (long)(bm + row) * Kd + k0 + c4 * 8;
            uint32_t doff = (row * HSTR + c4 * 4) * 4;
            cpa16(b0 + doff, Ahp + so, ok ? 16 : 0);
            if (NPASS == 3)
                cpa16(b0 + ASEG * 4 + doff, Alp + so, ok ? 16 : 0);
        }
        #pragma unroll
        for (int j = 0; j < 2; j++) {
            int q = tid + 256 * j;
            int row = q >> 2, c4 = q & 3;
            long so = (long)(bn + row) * Kd + k0 + c4 * 8;
            uint32_t doff = (row * HSTR + c4 * 4) * 4;
            cpa16(b0 + BH_OFF * 4 + doff, Bhp + so, 16);
            if (NPASS >= 2)
                cpa16(b0 + (BH_OFF + BSEG) * 4 + doff, Blp + so, 16);
        }
        asm volatile("cp.async.commit_group;" ::: "memory");
    };

    float c[2][NI][4];
    #pragma unroll
    for (int mi = 0; mi < 2; mi++)
        #pragma unroll
        for (int ni = 0; ni < NI; ni++)
            #pragma unroll
            for (int q = 0; q < 4; q++) c[mi][ni][q] = 0.f;

    int nK = Kd >> 5;
    load_stage(0, 0);
    load_stage(1, 32);

    for (int i = 0; i < nK; i++) {
        asm volatile("cp.async.wait_group 1;" ::: "memory");
        __syncthreads();

        const uint32_t* Ahi = sh + (i & 1) * STG;
        const uint32_t* Alo = Ahi + ASEG;
        const uint32_t* Bhi = Ahi + BH_OFF;
        const uint32_t* Blo = Bhi + BSEG;

        #pragma unroll
        for (int ks = 0; ks < 2; ks++) {
            int ko = ks * 8;
            uint32_t ah[2][4], al[2][4];
            #pragma unroll
            for (int mi = 0; mi < 2; mi++) {
                int r0 = wm + mi * 16 + g;
                int o0 = r0 * HSTR + ko + tg;
                int o1 = (r0 + 8) * HSTR + ko + tg;
                ah[mi][0] = Ahi[o0];     ah[mi][1] = Ahi[o1];
                ah[mi][2] = Ahi[o0 + 4]; ah[mi][3] = Ahi[o1 + 4];
                if (NPASS == 3) {
                    al[mi][0] = Alo[o0];     al[mi][1] = Alo[o1];
                    al[mi][2] = Alo[o0 + 4]; al[mi][3] = Alo[o1 + 4];
                }
            }
            uint32_t bh[NI][2], bl[NI][2];
            #pragma unroll
            for (int ni = 0; ni < NI; ni++) {
                int n = wn + ni * 8 + g;
                int o = n * HSTR + ko + tg;
                bh[ni][0] = Bhi[o]; bh[ni][1] = Bhi[o + 4];
                if (NPASS >= 2) { bl[ni][0] = Blo[o]; bl[ni][1] = Blo[o + 4]; }
            }
            #pragma unroll
            for (int mi = 0; mi < 2; mi++)
                #pragma unroll
                for (int ni = 0; ni < NI; ni++)
                    mma16816(c[mi][ni][0], c[mi][ni][1], c[mi][ni][2], c[mi][ni][3],
                             ah[mi][0], ah[mi][1], ah[mi][2], ah[mi][3],
                             bh[ni][0], bh[ni][1]);
            if (NPASS >= 2) {
                #pragma unroll
                for (int mi = 0; mi < 2; mi++)
                    #pragma unroll
                    for (int ni = 0; ni < NI; ni++)
                        mma16816(c[mi][ni][0], c[mi][ni][1], c[mi][ni][2], c[mi][ni][3],
                                 ah[mi][0], ah[mi][1], ah[mi][2], ah[mi][3],
                                 bl[ni][0], bl[ni][1]);
            }
            if (NPASS == 3) {
                #pragma unroll
                for (int mi = 0; mi < 2; mi++)
                    #pragma unroll
                    for (int ni = 0; ni < NI; ni++)
                        mma16816(c[mi][ni][0], c[mi][ni][1], c[mi][ni][2], c[mi][ni][3],
                                 al[mi][0], al[mi][1], al[mi][2], al[mi][3],
                                 bh[ni][0], bh[ni][1]);
            }
        }
        __syncthreads();
        if (i + 2 < nK) load_stage(i & 1, (i + 2) * 32);
        else asm volatile("cp.async.commit_group;" ::: "memory");
    }

    #pragma unroll
    for (int mi = 0; mi < 2; mi++) {
        int r0 = bm + wm + mi * 16 + g;
        #pragma unroll
        for (int ni = 0; ni < NI; ni++) {
            int col = bn + wn + ni * 8 + tg * 2;
            float v0 = c[mi][ni][0], v1 = c[mi][ni][1];
            float v2 = c[mi][ni][2], v3 = c[mi][ni][3];
            if (ACT) { v0 = gelu1(v0); v1 = gelu1(v1); v2 = gelu1(v2); v3 = gelu1(v3); }
            if (OUT >= 1) {
                __half h0, l0, h1, l1;
                if (r0 < Me) {
                    split_h(v0, h0, l0); split_h(v1, h1, l1);
                    long o = (long)e * sC + (long)r0 * ldc + col;
                    *(__half2*)&Ch[o] = __halves2half2(h0, h1);
                    if (OUT == 1) *(__half2*)&Cl[o] = __halves2half2(l0, l1);
                }
                if (r0 + 8 < Me) {
                    split_h(v2, h0, l0); split_h(v3, h1, l1);
                    long o = (long)e * sC + (long)(r0 + 8) * ldc + col;
                    *(__half2*)&Ch[o] = __halves2half2(h0, h1);
                    if (OUT == 1) *(__half2*)&Cl[o] = __halves2half2(l0, l1);
                }
            } else {
                long eb = (long)e * sC;
                if (r0 < Me)     *(float2*)&Cf[eb + (long)r0 * ldc + col]       = make_float2(v0, v1);
                if (r0 + 8 < Me) *(float2*)&Cf[eb + (long)(r0 + 8) * ldc + col] = make_float2(v2, v3);
            }
        }
    }
}

constexpr int ASEG64 = 64 * HSTR;
constexpr int SMEM_P3 = 2 * (2 * ASEG64 + 2 * BSEG) * 4;   // 61440 B
constexpr int SMEM_P1 = 2 * (ASEG64 + BSEG) * 4;           // 30720 B

// ---------------- fp16 single-pass GEMM for logits ----------------
constexpr int HSEG = 128 * HSTR;
constexpr int LSTAGE = 2 * HSEG;
constexpr int LGEMM_SMEM = 2 * LSTAGE * 4;

__global__ void __launch_bounds__(256, 2)
hgemm_logits(const __half* __restrict__ A, const __half* __restrict__ B,
             float* __restrict__ C, int Kd, int ldc)
{
    extern __shared__ uint32_t sh[];
    int bm = blockIdx.y * 128;
    int bn = blockIdx.x * 128;

    int tid = threadIdx.x;
    int wid = tid >> 5, lane = tid & 31;
    int g   = lane >> 2, tg = lane & 3;
    int wm  = (wid & 3) * 32;
    int wn  = (wid >> 2) * 64;

    uint32_t smu = s2u(sh);

    auto load_stage = [&](int s, int k0) {
        uint32_t b0 = smu + (s * LSTAGE) * 4;
        #pragma unroll
        for (int j = 0; j < 2; j++) {
            int q = tid + 256 * j;
            int row = q >> 2, c4 = q & 3;
            uint32_t doff = (row * HSTR + c4 * 4) * 4;
            cpa16(b0 + doff,            A + (long)(bm + row) * Kd + k0 + c4 * 8, 16);
            cpa16(b0 + HSEG * 4 + doff, B + (long)(bn + row) * Kd + k0 + c4 * 8, 16);
        }
        asm volatile("cp.async.commit_group;" ::: "memory");
    };

    float c[2][8][4];
    #pragma unroll
    for (int mi = 0; mi < 2; mi++)
        #pragma unroll
        for (int ni = 0; ni < 8; ni++)
            #pragma unroll
            for (int q = 0; q < 4; q++) c[mi][ni][q] = 0.f;

    int nK = Kd >> 5;
    load_stage(0, 0);
    load_stage(1, 32);

    for (int i = 0; i < nK; i++) {
        asm volatile("cp.async.wait_group 1;" ::: "memory");
        __syncthreads();

        const uint32_t* As = sh + (i & 1) * LSTAGE;
        const uint32_t* Bs = As + HSEG;

        #pragma unroll
        for (int ks = 0; ks < 2; ks++) {
            int ko = ks * 8;
            uint32_t a[2][4], b[8][2];
            #pragma unroll
            for (int mi = 0; mi < 2; mi++) {
                int r0 = wm + mi * 16 + g;
                int o0 = r0 * HSTR + ko + tg;
                int o1 = (r0 + 8) * HSTR + ko + tg;
                a[mi][0] = As[o0];     a[mi][1] = As[o1];
                a[mi][2] = As[o0 + 4]; a[mi][3] = As[o1 + 4];
            }
            #pragma unroll
            for (int ni = 0; ni < 8; ni++) {
                int n = wn + ni * 8 + g;
                int o = n * HSTR + ko + tg;
                b[ni][0] = Bs[o]; b[ni][1] = Bs[o + 4];
            }
            #pragma unroll
            for (int mi = 0; mi < 2; mi++)
                #pragma unroll
                for (int ni = 0; ni < 8; ni++)
                    mma16816(c[mi][ni][0], c[mi][ni][1], c[mi][ni][2], c[mi][ni][3],
                             a[mi][0], a[mi][1], a[mi][2], a[mi][3],
                             b[ni][0], b[ni][1]);
        }
        __syncthreads();
        if (i + 2 < nK) load_stage(i & 1, (i + 2) * 32);
        else asm volatile("cp.async.commit_group;" ::: "memory");
    }

    #pragma unroll
    for (int mi = 0; mi < 2; mi++) {
        int r0 = bm + wm + mi * 16 + g;
        #pragma unroll
        for (int ni = 0; ni < 8; ni++) {
            int col = bn + wn + ni * 8 + tg * 2;
            *(float2*)&C[(long)r0 * ldc + col]       = make_float2(c[mi][ni][0], c[mi][ni][1]);
            *(float2*)&C[(long)(r0 + 8) * ldc + col] = make_float2(c[mi][ni][2], c[mi][ni][3]);
        }
    }
}

// ---------------- launch ----------------
extern "C" void kernel_launch(void* const* d_in, const int* in_sizes, int n_in,
                              void* d_out, int out_size) {
    const int*   ids      = (const int*)  d_in[0];
    const float* embed_w  = (const float*)d_in[1];
    const float* router_w = (const float*)d_in[2];
    const float* w1       = (const float*)d_in[3];
    const float* w2       = (const float*)d_in[4];
    const float* lns      = (const float*)d_in[5];
    float* out = (float*)d_out;

    float *p_eout;
    __half *p_xinh, *p_xinl, *p_midh, *p_midl, *p_w1h, *p_w1l, *p_w2h, *p_w2l;
    __half *p_hnh, *p_ewh;
    int   *p_counts;
    cudaGetSymbolAddress((void**)&p_eout,   g_eout);
    cudaGetSymbolAddress((void**)&p_xinh,   g_xinh);
    cudaGetSymbolAddress((void**)&p_xinl,   g_xinl);
    cudaGetSymbolAddress((void**)&p_midh,   g_midh);
    cudaGetSymbolAddress((void**)&p_midl,   g_midl);
    cudaGetSymbolAddress((void**)&p_w1h,    g_w1h);
    cudaGetSymbolAddress((void**)&p_w1l,    g_w1l);
    cudaGetSymbolAddress((void**)&p_w2h,    g_w2h);
    cudaGetSymbolAddress((void**)&p_w2l,    g_w2l);
    cudaGetSymbolAddress((void**)&p_hnh,    g_hnh);
    cudaGetSymbolAddress((void**)&p_ewh,    g_ewh);
    cudaGetSymbolAddress((void**)&p_counts, g_counts);

    static cudaStream_t s1 = nullptr;
    static cudaEvent_t ev_fork = nullptr, ev_w1 = nullptr, ev_w2 = nullptr, ev_ew = nullptr;
    if (!s1) {
        cudaStreamCreateWithFlags(&s1, cudaStreamNonBlocking);
        cudaEventCreateWithFlags(&ev_fork, cudaEventDisableTiming);
        cudaEventCreateWithFlags(&ev_w1, cudaEventDisableTiming);
        cudaEventCreateWithFlags(&ev_w2, cudaEventDisableTiming);
        cudaEventCreateWithFlags(&ev_ew, cudaEventDisableTiming);
        cudaFuncSetAttribute(hgemm_ps<1,1,3,64>, cudaFuncAttributeMaxDynamicSharedMemorySize, SMEM_P3);
        cudaFuncSetAttribute(hgemm_ps<0,0,3,64>, cudaFuncAttributeMaxDynamicSharedMemorySize, SMEM_P3);
        cudaFuncSetAttribute(hgemm_ps<1,2,1,64>, cudaFuncAttributeMaxDynamicSharedMemorySize, SMEM_P1);
        cudaFuncSetAttribute(hgemm_ps<0,0,1,64>, cudaFuncAttributeMaxDynamicSharedMemorySize, SMEM_P1);
        cudaFuncSetAttribute(hgemm_logits, cudaFuncAttributeMaxDynamicSharedMemorySize, LGEMM_SMEM);
    }

    // side stream: weight prep overlaps hop-0 routing
    cudaEventRecord(ev_fork, 0);
    cudaStreamWaitEvent(s1, ev_fork, 0);
    split_transpose_kernel<<<dim3(cDFF / 32, cD / 32, cE), dim3(32, 8), 0, s1>>>(w1, p_w1h, p_w1l, cD, cDFF);
    cudaEventRecord(ev_w1, s1);
    split_transpose_kernel<<<dim3(cD / 32, cDFF / 32, cE), dim3(32, 8), 0, s1>>>(w2, p_w2h, p_w2l, cDFF, cD);
    cudaEventRecord(ev_w2, s1);
    ew_half_kernel<<<(int)(((long)cV * cD / 2 + 255) / 256), 256, 0, s1>>>(embed_w);
    cudaEventRecord(ev_ew, s1);

    // main pipeline (stream 0)
    rope_init_kernel<<<cT, 64>>>();
    embed_gather_kernel<<<(int)(((long)cT * cD / 4 + 255) / 256), 256>>>(ids, embed_w);

    // ---- hop 0 ----
    router_route_kernel<<<cT, 512>>>(router_w);
    capacity_kernel<<<cE, 256>>>();
    gather_rope_kernel<1><<<dim3(cCAP, cE), 256>>>();
    cudaStreamWaitEvent(0, ev_w1, 0);
    hgemm_ps<1,1,3,64><<<dim3(cDFF / 128, cCAP / 64, cE), 256, SMEM_P3>>>(
        p_xinh, p_xinl, p_w1h, p_w1l,
        nullptr, p_midh, p_midl,
        cD, cDFF,
        (long)cCAP * cD, (long)cDFF * cD, (long)cCAP * cDFF, p_counts);
    cudaStreamWaitEvent(0, ev_w2, 0);
    hgemm_ps<0,0,3,64><<<dim3(cD / 128, cCAP / 64, cE), 256, SMEM_P3>>>(
        p_midh, p_midl, p_w2h, p_w2l,
        p_eout, nullptr, nullptr,
        cDFF, cD,
        (long)cCAP * cDFF, (long)cD * cDFF, (long)cCAP * cD, p_counts);

    // ---- hop 1 (combine fused with router) ----
    combine_router_route_kernel<<<cT, 512>>>(router_w + (long)cD * cE);
    capacity_kernel<<<cE, 256>>>();
    gather_rope_kernel<0><<<dim3(cCAP, cE), 256>>>();    // lo never read in hop-1
    hgemm_ps<1,2,1,64><<<dim3(cDFF / 128, cCAP / 64, cE), 256, SMEM_P1>>>(
        p_xinh, p_xinl, p_w1h, p_w1l,
        nullptr, p_midh, p_midl,
        cD, cDFF,
        (long)cCAP * cD, (long)cDFF * cD, (long)cCAP * cDFF, p_counts);
    hgemm_ps<0,0,1,64><<<dim3(cD / 128, cCAP / 64, cE), 256, SMEM_P1>>>(
        p_midh, p_midl, p_w2h, p_w2l,
        p_eout, nullptr, nullptr,
        cDFF, cD,
        (long)cCAP * cDFF, (long)cD * cDFF, (long)cCAP * cD, p_counts);

    // ---- final combine + rmsnorm + logits ----
    combine_rmsnorm_kernel<<<cT, 256>>>(lns);
    cudaStreamWaitEvent(0, ev_ew, 0);
    hgemm_logits<<<dim3(cV / 128, cT / 128, 1), 256, LGEMM_SMEM>>>(
        p_hnh, p_ewh, out, cD, cV);
}

// round 17
// speedup vs baseline: 1.0510x; 1.0510x over previous
#include <cuda_runtime.h>
#include <cuda_fp16.h>
#include <math.h>
#include <stdint.h>

// ---------------- problem constants ----------------
constexpr int cT   = 2048;
constexpr int cD   = 1024;
constexpr int cV   = 32000;
constexpr int cE   = 16;
constexpr int cK   = 2;
constexpr int cCAP = 512;
constexpr int cDH  = 64;
constexpr int cDFF = 4096;

// ---------------- device scratch ----------------
__device__ float g_h   [cT * cD];
__device__ float g_cos [cT * cDH];
__device__ float g_sin [cT * cDH];
__device__ float g_logits[cT * cE];
__device__ float g_probs [cT * cE];
__device__ unsigned char g_mask[cT * cE];
__device__ int   g_kept_slot[cT * cE];
__device__ int   g_counts[cE];
__device__ int   g_etok[cE * cCAP];
__device__ float g_eout[(long)cE * cCAP * cD];
__device__ __half g_xinh[(long)cE * cCAP * cD];
__device__ __half g_midh[(long)cE * cCAP * cDFF];
__device__ __half g_midl[(long)cE * cCAP * cDFF];
__device__ __half g_w1h [(long)cE * cDFF * cD];
__device__ __half g_w1l [(long)cE * cDFF * cD];
__device__ __half g_w2h [(long)cE * cD * cDFF];
__device__ __half g_w2l [(long)cE * cD * cDFF];
__device__ __half g_hnh [cT * cD];
__device__ __half g_ewh [(long)cV * cD];

// ---------------- common helpers ----------------
__device__ __forceinline__ uint32_t s2u(const void* p) {
    uint32_t a;
    asm("{ .reg .u64 t; cvta.to.shared.u64 t, %1; cvt.u32.u64 %0, t; }" : "=r"(a) : "l"(p));
    return a;
}
__device__ __forceinline__ void mma16816(float& c0, float& c1, float& c2, float& c3,
                                         uint32_t a0, uint32_t a1, uint32_t a2, uint32_t a3,
                                         uint32_t b0, uint32_t b1) {
    asm volatile(
        "mma.sync.aligned.m16n8k16.row.col.f32.f16.f16.f32 "
        "{%0,%1,%2,%3}, {%4,%5,%6,%7}, {%8,%9}, {%0,%1,%2,%3};"
        : "+f"(c0), "+f"(c1), "+f"(c2), "+f"(c3)
        : "r"(a0), "r"(a1), "r"(a2), "r"(a3), "r"(b0), "r"(b1));
}
__device__ __forceinline__ void cpa16(uint32_t dst, const void* src, int sz) {
    asm volatile("cp.async.cg.shared.global [%0], [%1], 16, %2;"
                 :: "r"(dst), "l"(src), "r"(sz) : "memory");
}
__device__ __forceinline__ void split_h(float x, __half& hi, __half& lo) {
    hi = __float2half_rn(x);
    lo = __float2half_rn(x - __half2float(hi));
}
__device__ __forceinline__ float gelu1(float x) {
    return 0.5f * x * (1.0f + tanhf(0.7978845608028654f * (x + 0.044715f * x * x * x)));
}

// top-2 + softmax + mask/slot-reset for token t, given 16 logits (single thread)
__device__ __forceinline__ void route_token(int t, const float* l) {
    int i1 = 0; float v1 = l[0];
    #pragma unroll
    for (int e = 1; e < cE; e++) if (l[e] > v1) { v1 = l[e]; i1 = e; }
    int i2 = -1; float v2 = -INFINITY;
    #pragma unroll
    for (int e = 0; e < cE; e++) if (e != i1 && l[e] > v2) { v2 = l[e]; i2 = e; }
    float sum = 0.f; float p[cE];
    #pragma unroll
    for (int e = 0; e < cE; e++) { p[e] = expf(l[e] - v1); sum += p[e]; }
    float invs = 1.0f / sum;
    #pragma unroll
    for (int e = 0; e < cE; e++) {
        g_probs[t * cE + e] = p[e] * invs;
        g_mask [t * cE + e] = (e == i1 || e == i2) ? 1 : 0;
        g_kept_slot[t * cE + e] = -1;
    }
}

// ---------------- small kernels ----------------
__global__ void rope_init_kernel() {
    int t = blockIdx.x;
    int i = threadIdx.x;
    int j = 2 * (i & 31);
    float inv = powf(10000.0f, -(float)j / (float)cDH);
    float fr  = (float)t * inv;
    g_cos[t * cDH + i] = cosf(fr);
    g_sin[t * cDH + i] = sinf(fr);
}

__global__ void embed_gather_kernel(const int* __restrict__ ids,
                                    const float* __restrict__ ew) {
    long q = ((long)blockIdx.x * blockDim.x + threadIdx.x) * 4;
    if (q >= (long)cT * cD) return;
    int t = (int)(q >> 10);
    int d = (int)(q & (cD - 1));
    *(float4*)&g_h[q] = *(const float4*)&ew[(long)ids[t] * cD + d];
}

__global__ void ew_half_kernel(const float* __restrict__ ew) {
    long idx = ((long)blockIdx.x * blockDim.x + threadIdx.x) * 2;
    if (idx >= (long)cV * cD) return;
    float2 v = *(const float2*)&ew[idx];
    *(__half2*)&g_ewh[idx] = __halves2half2(__float2half_rn(v.x), __float2half_rn(v.y));
}

// fused: router logits + top-2 + softmax + slot reset (hop 0)
__global__ void router_route_kernel(const float* __restrict__ wr) {
    int t    = blockIdx.x;
    int e    = threadIdx.x >> 5;
    int lane = threadIdx.x & 31;
    __shared__ float lg[cE];
    float s = 0.f;
    const float* hp = &g_h[(long)t * cD];
    for (int d = lane; d < cD; d += 32)
        s += hp[d] * wr[(long)d * cE + e];
    #pragma unroll
    for (int o = 16; o; o >>= 1) s += __shfl_down_sync(0xffffffffu, s, o);
    if (lane == 0) { lg[e] = s; g_logits[t * cE + e] = s; }
    __syncthreads();
    if (threadIdx.x == 0) {
        route_token(t, lg);
        if (t < cE) g_counts[t] = 0;
    }
}

// fused: combine (prev hop) + router logits + top-2 + softmax (next hop)
__global__ void combine_router_route_kernel(const float* __restrict__ wr) {
    int t = blockIdx.x;
    __shared__ float hx[cD];
    __shared__ float lg[cE];
    __shared__ int   s_ne, s_ke[cK], s_ks[cK];
    __shared__ float s_kp[cK], s_rho;
    if (threadIdx.x == 0) {
        int ne = 0; float rho = 0.f;
        #pragma unroll
        for (int e = 0; e < cE; e++) {
            int sl = g_kept_slot[t * cE + e];
            if (sl >= 0) {
                float p = g_probs[t * cE + e];
                rho += p;
                if (ne < cK) { s_ke[ne] = e; s_ks[ne] = sl; s_kp[ne] = p; ne++; }
            }
        }
        s_ne = ne; s_rho = rho;
    }
    __syncthreads();
    int ne = s_ne; float rho = s_rho;
    for (int d = threadIdx.x; d < cD; d += 512) {
        float hv = g_h[(long)t * cD + d];
        float comb = 0.f;
        for (int q = 0; q < ne; q++)
            comb += s_kp[q] * g_eout[((long)(s_ke[q] * cCAP + s_ks[q])) * cD + d];
        float hn = hv + comb - rho * hv;
        hx[d] = hn;
        g_h[(long)t * cD + d] = hn;
    }
    __syncthreads();
    int e = threadIdx.x >> 5, lane = threadIdx.x & 31;
    float s = 0.f;
    for (int d = lane; d < cD; d += 32)
        s += hx[d] * wr[(long)d * cE + e];
    #pragma unroll
    for (int o = 16; o; o >>= 1) s += __shfl_down_sync(0xffffffffu, s, o);
    if (lane == 0) { lg[e] = s; g_logits[t * cE + e] = s; }
    __syncthreads();
    if (threadIdx.x == 0) {
        route_token(t, lg);
        if (t < cE) g_counts[t] = 0;
    }
}

// fused: final combine + rmsnorm -> fp16 (h never written back to global)
__global__ void combine_rmsnorm_kernel(const float* __restrict__ lns) {
    int t = blockIdx.x;
    __shared__ float red[256];
    __shared__ int   s_ne, s_ke[cK], s_ks[cK];
    __shared__ float s_kp[cK], s_rho;
    if (threadIdx.x == 0) {
        int ne = 0; float rho = 0.f;
        #pragma unroll
        for (int e = 0; e < cE; e++) {
            int sl = g_kept_slot[t * cE + e];
            if (sl >= 0) {
                float p = g_probs[t * cE + e];
                rho += p;
                if (ne < cK) { s_ke[ne] = e; s_ks[ne] = sl; s_kp[ne] = p; ne++; }
            }
        }
        s_ne = ne; s_rho = rho;
    }
    __syncthreads();
    int ne = s_ne; float rho = s_rho;
    float hn[4];
    float ss = 0.f;
    #pragma unroll
    for (int j = 0; j < 4; j++) {
        int d = threadIdx.x + 256 * j;
        float hv = g_h[(long)t * cD + d];
        float comb = 0.f;
        for (int q = 0; q < ne; q++)
            comb += s_kp[q] * g_eout[((long)(s_ke[q] * cCAP + s_ks[q])) * cD + d];
        hn[j] = hv + comb - rho * hv;
        ss += hn[j] * hn[j];
    }
    red[threadIdx.x] = ss;
    __syncthreads();
    #pragma unroll
    for (int o = 128; o; o >>= 1) {
        if (threadIdx.x < o) red[threadIdx.x] += red[threadIdx.x + o];
        __syncthreads();
    }
    float inv = rsqrtf(red[0] / (float)cD + 1e-6f);
    #pragma unroll
    for (int j = 0; j < 4; j++) {
        int d = threadIdx.x + 256 * j;
        g_hnh[(long)t * cD + d] = __float2half_rn(hn[j] * lns[d] * inv);
    }
}

__global__ void capacity_kernel() {
    int e = blockIdx.x;
    __shared__ int   cnt;
    __shared__ int   idx[cT];
    __shared__ float val[cT];
    if (threadIdx.x == 0) cnt = 0;
    __syncthreads();
    for (int t = threadIdx.x; t < cT; t += blockDim.x) {
        if (g_mask[t * cE + e]) {
            int p = atomicAdd(&cnt, 1);
            idx[p] = t;
            val[p] = g_logits[t * cE + e];
        }
    }
    __syncthreads();
    int n = cnt;
    for (int i = threadIdx.x; i < n; i += blockDim.x) {
        float v = val[i]; int t = idx[i];
        int rank = 0;
        for (int j = 0; j < n; j++) {
            float u = val[j]; int s = idx[j];
            rank += (u > v || (u == v && s < t)) ? 1 : 0;
        }
        if (rank < cCAP) {
            int slot = atomicAdd(&g_counts[e], 1);
            g_etok[e * cCAP + slot] = t;
            g_kept_slot[t * cE + e] = slot;
        }
    }
}

// gather + RoPE + fp16 (hi only — activation-lo is never consumed)
__global__ void gather_rope_kernel() {
    int c = blockIdx.x;
    int e = blockIdx.y;
    if (c >= g_counts[e]) return;
    int t = g_etok[e * cCAP + c];
    __shared__ float x[cD];
    for (int d = threadIdx.x; d < cD; d += blockDim.x) x[d] = g_h[(long)t * cD + d];
    __syncthreads();
    const float* cs = &g_cos[t * cDH];
    const float* sn = &g_sin[t * cDH];
    long base = ((long)(e * cCAP + c)) * cD;
    for (int dp = threadIdx.x; dp < cD / 2; dp += blockDim.x) {
        int d0 = dp * 2;
        float o[2];
        #pragma unroll
        for (int q = 0; q < 2; q++) {
            int d = d0 + q;
            int i = d & (cDH - 1);
            float r = (i < 32) ? -x[d + 32] : x[d - 32];
            o[q] = x[d] * cs[i] + r * sn[i];
        }
        *(__half2*)&g_xinh[base + d0] =
            __halves2half2(__float2half_rn(o[0]), __float2half_rn(o[1]));
    }
}

__global__ void split_transpose_kernel(const float* __restrict__ in,
                                       __half* __restrict__ oh, __half* __restrict__ ol,
                                       int R, int C) {
    __shared__ float tile[32][33];
    long eoff = (long)blockIdx.z * R * C;
    int c0 = blockIdx.x * 32, r0 = blockIdx.y * 32;
    int x = threadIdx.x, y = threadIdx.y;
    #pragma unroll
    for (int i = 0; i < 32; i += 8)
        tile[y + i][x] = in[eoff + (long)(r0 + y + i) * C + c0 + x];
    __syncthreads();
    if (x < 16) {
        #pragma unroll
        for (int i = 0; i < 32; i += 8) {
            int nl = y + i;
            float v0 = tile[2 * x][nl];
            float v1 = tile[2 * x + 1][nl];
            __half h0, l0, h1, l1;
            split_h(v0, h0, l0);
            split_h(v1, h1, l1);
            long o = eoff + (long)(c0 + nl) * R + r0 + 2 * x;
            *(__half2*)&oh[o] = __halves2half2(h0, h1);
            *(__half2*)&ol[o] = __halves2half2(l0, l1);
        }
    }
}

// ---------------- pre-split fp16 GEMM (experts) ----------------
// BM=64: 8 warps as 2M x 4N (warp tile 32x32).
// NPASS=3: ah*bh + ah*bl + al*bh ; NPASS=2: ah*bh + ah*bl ; NPASS=1: ah*bh.
// OUT: 0 = fp32, 1 = f16 hi+lo, 2 = f16 hi only.
constexpr int HSTR  = 20;
constexpr int BSEG  = 128 * HSTR;

template<int ACT, int OUT, int NPASS, int BM>
__global__ void __launch_bounds__(256, 2)
hgemm_ps(const __half* __restrict__ Ah, const __half* __restrict__ Al,
         const __half* __restrict__ Bh, const __half* __restrict__ Bl,
         float* __restrict__ Cf, __half* __restrict__ Ch, __half* __restrict__ Cl,
         int Kd, int ldc,
         long sA, long sB, long sC, const int* __restrict__ Mvec)
{
    constexpr int MW   = BM / 32;
    constexpr int NW   = 8 / MW;
    constexpr int NI   = 128 / (NW * 8);
    constexpr int ASEG = BM * HSTR;
    constexpr int ALO  = (NPASS == 3) ? ASEG : 0;
    constexpr int BH_OFF = ASEG + ALO;
    constexpr int BLO  = (NPASS >= 2) ? BSEG : 0;
    constexpr int STG  = BH_OFF + BSEG + BLO;

    extern __shared__ uint32_t sh[];
    int e  = blockIdx.z;
    int Me = Mvec[e];
    int bm = blockIdx.y * BM;
    if (bm >= Me) return;
    int bn = blockIdx.x * 128;
    const __half* Ahp = Ah + (long)e * sA;
    const __half* Alp = Al + (long)e * sA;
    const __half* Bhp = Bh + (long)e * sB;
    const __half* Blp = Bl + (long)e * sB;

    int tid = threadIdx.x;
    int wid = tid >> 5, lane = tid & 31;
    int g   = lane >> 2, tg = lane & 3;
    int wm  = (wid % MW) * 32;
    int wn  = (wid / MW) * (NI * 8);

    uint32_t smu = s2u(sh);

    auto load_stage = [&](int s, int k0) {
        uint32_t b0 = smu + (s * STG) * 4;
        #pragma unroll
        for (int j = 0; j < BM / 64; j++) {
            int q = tid + 256 * j;
            int row = q >> 2, c4 = q & 3;
            int ok = (bm + row) < Me;
            long so = (long)(bm + row) * Kd + k0 + c4 * 8;
            uint32_t doff = (row * HSTR + c4 * 4) * 4;
            cpa16(b0 + doff, Ahp + so, ok ? 16 : 0);
            if (NPASS == 3)
                cpa16(b0 + ASEG * 4 + doff, Alp + so, ok ? 16 : 0);
        }
        #pragma unroll
        for (int j = 0; j < 2; j++) {
            int q = tid + 256 * j;
            int row = q >> 2, c4 = q & 3;
            long so = (long)(bn + row) * Kd + k0 + c4 * 8;
            uint32_t doff = (row * HSTR + c4 * 4) * 4;
            cpa16(b0 + BH_OFF * 4 + doff, Bhp + so, 16);
            if (NPASS >= 2)
                cpa16(b0 + (BH_OFF + BSEG) * 4 + doff, Blp + so, 16);
        }
        asm volatile("cp.async.commit_group;" ::: "memory");
    };

    float c[2][NI][4];
    #pragma unroll
    for (int mi = 0; mi < 2; mi++)
        #pragma unroll
        for (int ni = 0; ni < NI; ni++)
            #pragma unroll
            for (int q = 0; q < 4; q++) c[mi][ni][q] = 0.f;

    int nK = Kd >> 5;
    load_stage(0, 0);
    load_stage(1, 32);

    for (int i = 0; i < nK; i++) {
        asm volatile("cp.async.wait_group 1;" ::: "memory");
        __syncthreads();

        const uint32_t* Ahi = sh + (i & 1) * STG;
        const uint32_t* Alo = Ahi + ASEG;
        const uint32_t* Bhi = Ahi + BH_OFF;
        const uint32_t* Blo = Bhi + BSEG;

        #pragma unroll
        for (int ks = 0; ks < 2; ks++) {
            int ko = ks * 8;
            uint32_t ah[2][4], al[2][4];
            #pragma unroll
            for (int mi = 0; mi < 2; mi++) {
                int r0 = wm + mi * 16 + g;
                int o0 = r0 * HSTR + ko + tg;
                int o1 = (r0 + 8) * HSTR + ko + tg;
                ah[mi][0] = Ahi[o0];     ah[mi][1] = Ahi[o1];
                ah[mi][2] = Ahi[o0 + 4]; ah[mi][3] = Ahi[o1 + 4];
                if (NPASS == 3) {
                    al[mi][0] = Alo[o0];     al[mi][1] = Alo[o1];
                    al[mi][2] = Alo[o0 + 4]; al[mi][3] = Alo[o1 + 4];
                }
            }
            uint32_t bh[NI][2], bl[NI][2];
            #pragma unroll
            for (int ni = 0; ni < NI; ni++) {
                int n = wn + ni * 8 + g;
                int o = n * HSTR + ko + tg;
                bh[ni][0] = Bhi[o]; bh[ni][1] = Bhi[o + 4];
                if (NPASS >= 2) { bl[ni][0] = Blo[o]; bl[ni][1] = Blo[o + 4]; }
            }
            #pragma unroll
            for (int mi = 0; mi < 2; mi++)
                #pragma unroll
                for (int ni = 0; ni < NI; ni++)
                    mma16816(c[mi][ni][0], c[mi][ni][1], c[mi][ni][2], c[mi][ni][3],
                             ah[mi][0], ah[mi][1], ah[mi][2], ah[mi][3],
                             bh[ni][0], bh[ni][1]);
            if (NPASS >= 2) {
                #pragma unroll
                for (int mi = 0; mi < 2; mi++)
                    #pragma unroll
                    for (int ni = 0; ni < NI; ni++)
                        mma16816(c[mi][ni][0], c[mi][ni][1], c[mi][ni][2], c[mi][ni][3],
                                 ah[mi][0], ah[mi][1], ah[mi][2], ah[mi][3],
                                 bl[ni][0], bl[ni][1]);
            }
            if (NPASS == 3) {
                #pragma unroll
                for (int mi = 0; mi < 2; mi++)
                    #pragma unroll
                    for (int ni = 0; ni < NI; ni++)
                        mma16816(c[mi][ni][0], c[mi][ni][1], c[mi][ni][2], c[mi][ni][3],
                                 al[mi][0], al[mi][1], al[mi][2], al[mi][3],
                                 bh[ni][0], bh[ni][1]);
            }
        }
        __syncthreads();
        if (i + 2 < nK) load_stage(i & 1, (i + 2) * 32);
        else asm volatile("cp.async.commit_group;" ::: "memory");
    }

    #pragma unroll
    for (int mi = 0; mi < 2; mi++) {
        int r0 = bm + wm + mi * 16 + g;
        #pragma unroll
        for (int ni = 0; ni < NI; ni++) {
            int col = bn + wn + ni * 8 + tg * 2;
            float v0 = c[mi][ni][0], v1 = c[mi][ni][1];
            float v2 = c[mi][ni][2], v3 = c[mi][ni][3];
            if (ACT) { v0 = gelu1(v0); v1 = gelu1(v1); v2 = gelu1(v2); v3 = gelu1(v3); }
            if (OUT >= 1) {
                __half h0, l0, h1, l1;
                if (r0 < Me) {
                    split_h(v0, h0, l0); split_h(v1, h1, l1);
                    long o = (long)e * sC + (long)r0 * ldc + col;
                    *(__half2*)&Ch[o] = __halves2half2(h0, h1);
                    if (OUT == 1) *(__half2*)&Cl[o] = __halves2half2(l0, l1);
                }
                if (r0 + 8 < Me) {
                    split_h(v2, h0, l0); split_h(v3, h1, l1);
                    long o = (long)e * sC + (long)(r0 + 8) * ldc + col;
                    *(__half2*)&Ch[o] = __halves2half2(h0, h1);
                    if (OUT == 1) *(__half2*)&Cl[o] = __halves2half2(l0, l1);
                }
            } else {
                long eb = (long)e * sC;
                if (r0 < Me)     *(float2*)&Cf[eb + (long)r0 * ldc + col]       = make_float2(v0, v1);
                if (r0 + 8 < Me) *(float2*)&Cf[eb + (long)(r0 + 8) * ldc + col] = make_float2(v2, v3);
            }
        }
    }
}

constexpr int ASEG64 = 64 * HSTR;
constexpr int SMEM_P3 = 2 * (2 * ASEG64 + 2 * BSEG) * 4;   // 61440 B
constexpr int SMEM_P2 = 2 * (ASEG64 + 2 * BSEG) * 4;       // 51200 B
constexpr int SMEM_P1 = 2 * (ASEG64 + BSEG) * 4;           // 30720 B

// ---------------- fp16 single-pass GEMM for logits ----------------
constexpr int HSEG = 128 * HSTR;
constexpr int LSTAGE = 2 * HSEG;
constexpr int LGEMM_SMEM = 2 * LSTAGE * 4;

__global__ void __launch_bounds__(256, 2)
hgemm_logits(const __half* __restrict__ A, const __half* __restrict__ B,
             float* __restrict__ C, int Kd, int ldc)
{
    extern __shared__ uint32_t sh[];
    int bm = blockIdx.y * 128;
    int bn = blockIdx.x * 128;

    int tid = threadIdx.x;
    int wid = tid >> 5, lane = tid & 31;
    int g   = lane >> 2, tg = lane & 3;
    int wm  = (wid & 3) * 32;
    int wn  = (wid >> 2) * 64;

    uint32_t smu = s2u(sh);

    auto load_stage = [&](int s, int k0) {
        uint32_t b0 = smu + (s * LSTAGE) * 4;
        #pragma unroll
        for (int j = 0; j < 2; j++) {
            int q = tid + 256 * j;
            int row = q >> 2, c4 = q & 3;
            uint32_t doff = (row * HSTR + c4 * 4) * 4;
            cpa16(b0 + doff,            A + (long)(bm + row) * Kd + k0 + c4 * 8, 16);
            cpa16(b0 + HSEG * 4 + doff, B + (long)(bn + row) * Kd + k0 + c4 * 8, 16);
        }
        asm volatile("cp.async.commit_group;" ::: "memory");
    };

    float c[2][8][4];
    #pragma unroll
    for (int mi = 0; mi < 2; mi++)
        #pragma unroll
        for (int ni = 0; ni < 8; ni++)
            #pragma unroll
            for (int q = 0; q < 4; q++) c[mi][ni][q] = 0.f;

    int nK = Kd >> 5;
    load_stage(0, 0);
    load_stage(1, 32);

    for (int i = 0; i < nK; i++) {
        asm volatile("cp.async.wait_group 1;" ::: "memory");
        __syncthreads();

        const uint32_t* As = sh + (i & 1) * LSTAGE;
        const uint32_t* Bs = As + HSEG;

        #pragma unroll
        for (int ks = 0; ks < 2; ks++) {
            int ko = ks * 8;
            uint32_t a[2][4], b[8][2];
            #pragma unroll
            for (int mi = 0; mi < 2; mi++) {
                int r0 = wm + mi * 16 + g;
                int o0 = r0 * HSTR + ko + tg;
                int o1 = (r0 + 8) * HSTR + ko + tg;
                a[mi][0] = As[o0];     a[mi][1] = As[o1];
                a[mi][2] = As[o0 + 4]; a[mi][3] = As[o1 + 4];
            }
            #pragma unroll
            for (int ni = 0; ni < 8; ni++) {
                int n = wn + ni * 8 + g;
                int o = n * HSTR + ko + tg;
                b[ni][0] = Bs[o]; b[ni][1] = Bs[o + 4];
            }
            #pragma unroll
            for (int mi = 0; mi < 2; mi++)
                #pragma unroll
                for (int ni = 0; ni < 8; ni++)
                    mma16816(c[mi][ni][0], c[mi][ni][1], c[mi][ni][2], c[mi][ni][3],
                             a[mi][0], a[mi][1], a[mi][2], a[mi][3],
                             b[ni][0], b[ni][1]);
        }
        __syncthreads();
        if (i + 2 < nK) load_stage(i & 1, (i + 2) * 32);
        else asm volatile("cp.async.commit_group;" ::: "memory");
    }

    #pragma unroll
    for (int mi = 0; mi < 2; mi++) {
        int r0 = bm + wm + mi * 16 + g;
        #pragma unroll
        for (int ni = 0; ni < 8; ni++) {
            int col = bn + wn + ni * 8 + tg * 2;
            *(float2*)&C[(long)r0 * ldc + col]       = make_float2(c[mi][ni][0], c[mi][ni][1]);
            *(float2*)&C[(long)(r0 + 8) * ldc + col] = make_float2(c[mi][ni][2], c[mi][ni][3]);
        }
    }
}

// ---------------- launch ----------------
extern "C" void kernel_launch(void* const* d_in, const int* in_sizes, int n_in,
                              void* d_out, int out_size) {
    const int*   ids      = (const int*)  d_in[0];
    const float* embed_w  = (const float*)d_in[1];
    const float* router_w = (const float*)d_in[2];
    const float* w1       = (const float*)d_in[3];
    const float* w2       = (const float*)d_in[4];
    const float* lns      = (const float*)d_in[5];
    float* out = (float*)d_out;

    float *p_eout;
    __half *p_xinh, *p_midh, *p_midl, *p_w1h, *p_w1l, *p_w2h, *p_w2l;
    __half *p_hnh, *p_ewh;
    int   *p_counts;
    cudaGetSymbolAddress((void**)&p_eout,   g_eout);
    cudaGetSymbolAddress((void**)&p_xinh,   g_xinh);
    cudaGetSymbolAddress((void**)&p_midh,   g_midh);
    cudaGetSymbolAddress((void**)&p_midl,   g_midl);
    cudaGetSymbolAddress((void**)&p_w1h,    g_w1h);
    cudaGetSymbolAddress((void**)&p_w1l,    g_w1l);
    cudaGetSymbolAddress((void**)&p_w2h,    g_w2h);
    cudaGetSymbolAddress((void**)&p_w2l,    g_w2l);
    cudaGetSymbolAddress((void**)&p_hnh,    g_hnh);
    cudaGetSymbolAddress((void**)&p_ewh,    g_ewh);
    cudaGetSymbolAddress((void**)&p_counts, g_counts);

    static cudaStream_t s1 = nullptr;
    static cudaEvent_t ev_fork = nullptr, ev_w1 = nullptr, ev_w2 = nullptr, ev_ew = nullptr;
    if (!s1) {
        cudaStreamCreateWithFlags(&s1, cudaStreamNonBlocking);
        cudaEventCreateWithFlags(&ev_fork, cudaEventDisableTiming);
        cudaEventCreateWithFlags(&ev_w1, cudaEventDisableTiming);
        cudaEventCreateWithFlags(&ev_w2, cudaEventDisableTiming);
        cudaEventCreateWithFlags(&ev_ew, cudaEventDisableTiming);
        cudaFuncSetAttribute(hgemm_ps<1,1,2,64>, cudaFuncAttributeMaxDynamicSharedMemorySize, SMEM_P2);
        cudaFuncSetAttribute(hgemm_ps<0,0,3,64>, cudaFuncAttributeMaxDynamicSharedMemorySize, SMEM_P3);
        cudaFuncSetAttribute(hgemm_ps<1,2,1,64>, cudaFuncAttributeMaxDynamicSharedMemorySize, SMEM_P1);
        cudaFuncSetAttribute(hgemm_ps<0,0,1,64>, cudaFuncAttributeMaxDynamicSharedMemorySize, SMEM_P1);
        cudaFuncSetAttribute(hgemm_logits, cudaFuncAttributeMaxDynamicSharedMemorySize, LGEMM_SMEM);
    }

    // side stream: weight prep overlaps hop-0 routing
    cudaEventRecord(ev_fork, 0);
    cudaStreamWaitEvent(s1, ev_fork, 0);
    split_transpose_kernel<<<dim3(cDFF / 32, cD / 32, cE), dim3(32, 8), 0, s1>>>(w1, p_w1h, p_w1l, cD, cDFF);
    cudaEventRecord(ev_w1, s1);
    split_transpose_kernel<<<dim3(cD / 32, cDFF / 32, cE), dim3(32, 8), 0, s1>>>(w2, p_w2h, p_w2l, cDFF, cD);
    cudaEventRecord(ev_w2, s1);
    ew_half_kernel<<<(int)(((long)cV * cD / 2 + 255) / 256), 256, 0, s1>>>(embed_w);
    cudaEventRecord(ev_ew, s1);

    // main pipeline (stream 0)
    rope_init_kernel<<<cT, 64>>>();
    embed_gather_kernel<<<(int)(((long)cT * cD / 4 + 255) / 256), 256>>>(ids, embed_w);

    // ---- hop 0 ----
    router_route_kernel<<<cT, 512>>>(router_w);
    capacity_kernel<<<cE, 256>>>();
    gather_rope_kernel<<<dim3(cCAP, cE), 256>>>();
    cudaStreamWaitEvent(0, ev_w1, 0);
    // GEMM1: 2-pass (ah*bh + ah*bl) — activation-lo dropped (flip risk ~0.4 expected)
    hgemm_ps<1,1,2,64><<<dim3(cDFF / 128, cCAP / 64, cE), 256, SMEM_P2>>>(
        p_xinh, nullptr, p_w1h, p_w1l,
        nullptr, p_midh, p_midl,
        cD, cDFF,
        (long)cCAP * cD, (long)cDFF * cD, (long)cCAP * cDFF, p_counts);
    cudaStreamWaitEvent(0, ev_w2, 0);
    // GEMM2: full 3-pass (routing-critical output)
    hgemm_ps<0,0,3,64><<<dim3(cD / 128, cCAP / 64, cE), 256, SMEM_P3>>>(
        p_midh, p_midl, p_w2h, p_w2l,
        p_eout, nullptr, nullptr,
        cDFF, cD,
        (long)cCAP * cDFF, (long)cD * cDFF, (long)cCAP * cD, p_counts);

    // ---- hop 1 (combine fused with router) ----
    combine_router_route_kernel<<<cT, 512>>>(router_w + (long)cD * cE);
    capacity_kernel<<<cE, 256>>>();
    gather_rope_kernel<<<dim3(cCAP, cE), 256>>>();
    hgemm_ps<1,2,1,64><<<dim3(cDFF / 128, cCAP / 64, cE), 256, SMEM_P1>>>(
        p_xinh, nullptr, p_w1h, p_w1l,
        nullptr, p_midh, p_midl,
        cD, cDFF,
        (long)cCAP * cD, (long)cDFF * cD, (long)cCAP * cDFF, p_counts);
    hgemm_ps<0,0,1,64><<<dim3(cD / 128, cCAP / 64, cE), 256, SMEM_P1>>>(
        p_midh, p_midl, p_w2h, p_w2l,
        p_eout, nullptr, nullptr,
        cDFF, cD,
        (long)cCAP * cDFF, (long)cD * cDFF, (long)cCAP * cD, p_counts);

    // ---- final combine + rmsnorm + logits ----
    combine_rmsnorm_kernel<<<cT, 256>>>(lns);
    cudaStreamWaitEvent(0, ev_ew, 0);
    hgemm_logits<<<dim3(cV / 128, cT / 128, 1), 256, LGEMM_SMEM>>>(
        p_hnh, p_ewh, out, cD, cV);
}